// round 1
// baseline (speedup 1.0000x reference)
#include <cuda_runtime.h>

// LIF SNN scan: T=1024 timesteps, B*N = 65536 independent columns.
// out layout: [ spikes (T*BN) | v_final (BN) | i_final (BN) ]

#define T_STEPS 1024
#define BN      65536

__global__ __launch_bounds__(128, 8)
void snn_lif_kernel(const float* __restrict__ x, float* __restrict__ out) {
    const int idx = blockIdx.x * blockDim.x + threadIdx.x;  // column id 0..BN-1
    const float* xp = x + idx;
    float*       zp = out + idx;

    float v   = 0.0f;   // membrane potential
    float cur = 0.0f;   // synaptic current

    // dt*tau_mem_inv = 0.1, (1 - dt*tau_syn_inv) = 0.8, v_th = 1, v_reset = 0
    #pragma unroll 16
    for (int t = 0; t < T_STEPS; ++t) {
        // independent of loop-carried state -> ptxas front-batches these (high MLP)
        const float xt = __ldg(xp + (long)t * BN);

        const float v_dec = fmaf(0.1f, cur - v, v);       // v + 0.1*((0-v)+i)
        const bool  fired = (v_dec > 1.0f);               // strict >, matches (x>0)
        const float z     = fired ? 1.0f : 0.0f;
        v   = fired ? 0.0f : v_dec;                       // reset to 0
        cur = fmaf(cur, 0.8f, xt);                        // i*0.8 + x_t

        zp[(long)t * BN] = z;
    }

    // final state after the full scan
    out[(long)T_STEPS * BN + idx]      = v;
    out[(long)T_STEPS * BN + BN + idx] = cur;
}

extern "C" void kernel_launch(void* const* d_in, const int* in_sizes, int n_in,
                              void* d_out, int out_size) {
    const float* x   = (const float*)d_in[0];
    float*       out = (float*)d_out;
    (void)in_sizes; (void)n_in; (void)out_size;

    snn_lif_kernel<<<BN / 128, 128>>>(x, out);
}